// round 2
// baseline (speedup 1.0000x reference)
#include <cuda_runtime.h>

// GraphDecoder (NRI decoder) fused fp32 kernels for sm_103a.
// Uses packed fma.rn.f32x2 to double fp32 FMA throughput.

#define BB 32
#define NN 64
#define FF 128
#define KK 4
#define EE 4032          // N*(N-1)
#define XSTR 260         // padded row stride for 256-wide smem tiles
#define AUGSTR 388       // padded row stride for 384-wide tile
#define P1STR 260

// scratch: aggregated messages [B, N, 256] (2 MB, static device global)
__device__ float g_agg[BB * NN * 256];

// ---------- packed f32x2 helpers ----------
__device__ __forceinline__ unsigned long long pack2(float x) {
    unsigned long long r;
    asm("mov.b64 %0, {%1, %1};" : "=l"(r) : "f"(x));
    return r;
}
__device__ __forceinline__ unsigned long long packab(float a, float b) {
    unsigned long long r;
    asm("mov.b64 %0, {%1, %2};" : "=l"(r) : "f"(a), "f"(b));
    return r;
}
__device__ __forceinline__ void unpack2(unsigned long long v, float& a, float& b) {
    asm("mov.b64 {%0, %1}, %2;" : "=f"(a), "=f"(b) : "l"(v));
}
__device__ __forceinline__ unsigned long long fma2(unsigned long long a,
                                                   unsigned long long b,
                                                   unsigned long long c) {
    unsigned long long d;
    asm("fma.rn.f32x2 %0, %1, %2, %3;" : "=l"(d) : "l"(a), "l"(b), "l"(c));
    return d;
}

// =====================================================================
// Kernel 1: per-edge 2-layer MLP over K edge types, fused with gather,
// rel_type weighting and receiver-node aggregation.
// Block = (node n, batch b). 63 real edges + 1 dummy row. 256 threads.
// Micro-tile: 8 edges x 8 cols per thread (as 4 f32x2 pairs).
// =====================================================================
__global__ void __launch_bounds__(256, 1)
edge_mlp_kernel(const float* __restrict__ inputs,
                const float* __restrict__ rel_type,
                const float* __restrict__ W1, const float* __restrict__ b1,
                const float* __restrict__ W2, const float* __restrict__ b2,
                float* __restrict__ agg)
{
    extern __shared__ float sm[];
    float* Xs  = sm;                    // [64][XSTR]  pre_msg (recv|send)
    float* Hs  = Xs + 64 * XSTR;        // [64][XSTR]  layer-1 activations
    float* Wc  = Hs + 64 * XSTR;        // [32][256]   streamed weight chunk
    float* rts = Wc + 32 * 256;         // [64][4]     rel_type tile

    const int n   = blockIdx.x;
    const int b   = blockIdx.y;
    const int tid = threadIdx.x;
    const int cg  = tid & 31;           // column group 0..31
    const int er  = tid >> 5;           // edge-row group 0..7
    const int col0 = cg << 3;

    // ---- gather X: row le -> edge e = 63n + le (le<63), row 63 dummy 0 ----
    const float* inb = inputs + (size_t)b * NN * FF;
    for (int idx = tid; idx < 64 * 64; idx += 256) {
        int le = idx >> 6, c4 = idx & 63;
        float4 v = make_float4(0.f, 0.f, 0.f, 0.f);
        if (le < 63) {
            if (c4 < 32) {
                v = *(const float4*)(inb + n * FF + (c4 << 2));            // receiver
            } else {
                int j = le + (le >= n);                                     // sender
                v = *(const float4*)(inb + j * FF + ((c4 - 32) << 2));
            }
        }
        *(float4*)(Xs + le * XSTR + (c4 << 2)) = v;
    }
    {
        int le = tid >> 2, k = tid & 3;
        rts[tid] = (le < 63) ? rel_type[((size_t)b * EE + n * 63 + le) * KK + k] : 0.f;
    }

    float aggp[8];
#pragma unroll
    for (int j = 0; j < 8; ++j) aggp[j] = 0.f;

#pragma unroll 1
    for (int k = 0; k < KK; ++k) {
        const float* W1k = W1 + k * 65536;
        const float* W2k = W2 + k * 65536;

        // hb = b1 + recvFeat @ W1[0:128]  (edge-independent half of layer 1)
        unsigned long long hb[4];
        {
            float4 t0 = *(const float4*)(b1 + k * 256 + col0);
            float4 t1 = *(const float4*)(b1 + k * 256 + col0 + 4);
            hb[0] = packab(t0.x, t0.y); hb[1] = packab(t0.z, t0.w);
            hb[2] = packab(t1.x, t1.y); hb[3] = packab(t1.z, t1.w);
        }
#pragma unroll 1
        for (int fc = 0; fc < 4; ++fc) {
            __syncthreads();
            const float* wsrc = W1k + fc * 32 * 256;
            for (int idx = tid; idx < 32 * 64; idx += 256)
                *(float4*)(Wc + ((idx >> 6) << 8) + ((idx & 63) << 2)) =
                    *(const float4*)(wsrc + ((idx >> 6) << 8) + ((idx & 63) << 2));
            __syncthreads();
#pragma unroll 8
            for (int f = 0; f < 32; ++f) {
                unsigned long long xp = pack2(Xs[fc * 32 + f]);   // row 0 recv feats
                const float* wrow = Wc + (f << 8) + col0;
                ulonglong2 wA = *(const ulonglong2*)(wrow);
                ulonglong2 wB = *(const ulonglong2*)(wrow + 4);
                hb[0] = fma2(xp, wA.x, hb[0]); hb[1] = fma2(xp, wA.y, hb[1]);
                hb[2] = fma2(xp, wB.x, hb[2]); hb[3] = fma2(xp, wB.y, hb[3]);
            }
        }

        // per-edge sender half of layer 1
        unsigned long long acc[8][4];
#pragma unroll
        for (int i = 0; i < 8; ++i) {
            acc[i][0] = hb[0]; acc[i][1] = hb[1]; acc[i][2] = hb[2]; acc[i][3] = hb[3];
        }
#pragma unroll 1
        for (int fc = 4; fc < 8; ++fc) {
            __syncthreads();
            const float* wsrc = W1k + fc * 32 * 256;
            for (int idx = tid; idx < 32 * 64; idx += 256)
                *(float4*)(Wc + ((idx >> 6) << 8) + ((idx & 63) << 2)) =
                    *(const float4*)(wsrc + ((idx >> 6) << 8) + ((idx & 63) << 2));
            __syncthreads();
#pragma unroll 8
            for (int f = 0; f < 32; ++f) {
                const float* wrow = Wc + (f << 8) + col0;
                ulonglong2 wA = *(const ulonglong2*)(wrow);
                ulonglong2 wB = *(const ulonglong2*)(wrow + 4);
#pragma unroll
                for (int i = 0; i < 8; ++i) {
                    unsigned long long xp = pack2(Xs[(er * 8 + i) * XSTR + fc * 32 + f]);
                    acc[i][0] = fma2(xp, wA.x, acc[i][0]);
                    acc[i][1] = fma2(xp, wA.y, acc[i][1]);
                    acc[i][2] = fma2(xp, wB.x, acc[i][2]);
                    acc[i][3] = fma2(xp, wB.y, acc[i][3]);
                }
            }
        }

        // relu -> Hs
#pragma unroll
        for (int i = 0; i < 8; ++i) {
            float4 v0, v1;
            unpack2(acc[i][0], v0.x, v0.y); unpack2(acc[i][1], v0.z, v0.w);
            unpack2(acc[i][2], v1.x, v1.y); unpack2(acc[i][3], v1.z, v1.w);
            v0.x = fmaxf(v0.x, 0.f); v0.y = fmaxf(v0.y, 0.f);
            v0.z = fmaxf(v0.z, 0.f); v0.w = fmaxf(v0.w, 0.f);
            v1.x = fmaxf(v1.x, 0.f); v1.y = fmaxf(v1.y, 0.f);
            v1.z = fmaxf(v1.z, 0.f); v1.w = fmaxf(v1.w, 0.f);
            *(float4*)(Hs + (er * 8 + i) * XSTR + col0)     = v0;
            *(float4*)(Hs + (er * 8 + i) * XSTR + col0 + 4) = v1;
        }

        // layer 2
        unsigned long long a2[8][4];
        {
            float4 t0 = *(const float4*)(b2 + k * 256 + col0);
            float4 t1 = *(const float4*)(b2 + k * 256 + col0 + 4);
            unsigned long long c0 = packab(t0.x, t0.y), c1 = packab(t0.z, t0.w);
            unsigned long long c2 = packab(t1.x, t1.y), c3 = packab(t1.z, t1.w);
#pragma unroll
            for (int i = 0; i < 8; ++i) {
                a2[i][0] = c0; a2[i][1] = c1; a2[i][2] = c2; a2[i][3] = c3;
            }
        }
#pragma unroll 1
        for (int fc = 0; fc < 8; ++fc) {
            __syncthreads();   // also guarantees Hs writes visible on fc==0
            const float* wsrc = W2k + fc * 32 * 256;
            for (int idx = tid; idx < 32 * 64; idx += 256)
                *(float4*)(Wc + ((idx >> 6) << 8) + ((idx & 63) << 2)) =
                    *(const float4*)(wsrc + ((idx >> 6) << 8) + ((idx & 63) << 2));
            __syncthreads();
#pragma unroll 8
            for (int f = 0; f < 32; ++f) {
                const float* wrow = Wc + (f << 8) + col0;
                ulonglong2 wA = *(const ulonglong2*)(wrow);
                ulonglong2 wB = *(const ulonglong2*)(wrow + 4);
#pragma unroll
                for (int i = 0; i < 8; ++i) {
                    unsigned long long xp = pack2(Hs[(er * 8 + i) * XSTR + fc * 32 + f]);
                    a2[i][0] = fma2(xp, wA.x, a2[i][0]);
                    a2[i][1] = fma2(xp, wA.y, a2[i][1]);
                    a2[i][2] = fma2(xp, wB.x, a2[i][2]);
                    a2[i][3] = fma2(xp, wB.y, a2[i][3]);
                }
            }
        }

        // relu, rel_type weighting, accumulate node aggregation
#pragma unroll
        for (int i = 0; i < 8; ++i) {
            float w = rts[(er * 8 + i) * 4 + k];
            float x0, x1;
            unpack2(a2[i][0], x0, x1); aggp[0] += w * fmaxf(x0, 0.f); aggp[1] += w * fmaxf(x1, 0.f);
            unpack2(a2[i][1], x0, x1); aggp[2] += w * fmaxf(x0, 0.f); aggp[3] += w * fmaxf(x1, 0.f);
            unpack2(a2[i][2], x0, x1); aggp[4] += w * fmaxf(x0, 0.f); aggp[5] += w * fmaxf(x1, 0.f);
            unpack2(a2[i][3], x0, x1); aggp[6] += w * fmaxf(x0, 0.f); aggp[7] += w * fmaxf(x1, 0.f);
        }
    }

    // reduce aggp over the 8 edge-row groups (reuse Wc as scratch)
    __syncthreads();
#pragma unroll
    for (int j = 0; j < 8; ++j) Wc[(er << 8) + col0 + j] = aggp[j];
    __syncthreads();
    {
        float s = 0.f;
#pragma unroll
        for (int r = 0; r < 8; ++r) s += Wc[(r << 8) + tid];
        agg[((size_t)b * NN + n) * 256 + tid] = s;
    }
}

// =====================================================================
// Kernel 2: output MLP 384->256->256->128 + residual.
// Block = (half of nodes, batch b): 32 rows, 128 threads, 8x8 micro-tiles.
// =====================================================================
__global__ void __launch_bounds__(128, 1)
out_mlp_kernel(const float* __restrict__ inputs, const float* __restrict__ agg,
               const float* __restrict__ Wo1, const float* __restrict__ bo1,
               const float* __restrict__ Wo2, const float* __restrict__ bo2,
               const float* __restrict__ Wo3, const float* __restrict__ bo3,
               float* __restrict__ out)
{
    extern __shared__ float sm[];
    float* augS = sm;                     // [32][AUGSTR] aug, later reused for p2
    float* p1S  = augS + 32 * AUGSTR;     // [32][P1STR]
    float* Wc   = p1S + 32 * P1STR;       // [32][256]

    const int half = blockIdx.x;
    const int b    = blockIdx.y;
    const int r0   = half * 32;
    const int tid  = threadIdx.x;
    const int cg   = tid & 31;
    const int er   = tid >> 5;            // 0..3
    const int col0 = cg << 3;

    // load aug = [inputs | agg]
    for (int idx = tid; idx < 32 * 96; idx += 128) {
        int r = idx / 96, c4 = idx % 96;
        float4 v;
        if (c4 < 32)
            v = *(const float4*)(inputs + ((size_t)(b * NN) + r0 + r) * FF + (c4 << 2));
        else
            v = *(const float4*)(agg + ((size_t)(b * NN) + r0 + r) * 256 + ((c4 - 32) << 2));
        *(float4*)(augS + r * AUGSTR + (c4 << 2)) = v;
    }

    // ---- layer 1: 384 -> 256 ----
    unsigned long long acc[8][4];
    {
        float4 t0 = *(const float4*)(bo1 + col0);
        float4 t1 = *(const float4*)(bo1 + col0 + 4);
        unsigned long long c0 = packab(t0.x, t0.y), c1 = packab(t0.z, t0.w);
        unsigned long long c2 = packab(t1.x, t1.y), c3 = packab(t1.z, t1.w);
#pragma unroll
        for (int i = 0; i < 8; ++i) {
            acc[i][0] = c0; acc[i][1] = c1; acc[i][2] = c2; acc[i][3] = c3;
        }
    }
#pragma unroll 1
    for (int fc = 0; fc < 12; ++fc) {
        __syncthreads();
        const float* wsrc = Wo1 + fc * 32 * 256;
        for (int idx = tid; idx < 32 * 64; idx += 128)
            *(float4*)(Wc + ((idx >> 6) << 8) + ((idx & 63) << 2)) =
                *(const float4*)(wsrc + ((idx >> 6) << 8) + ((idx & 63) << 2));
        __syncthreads();
#pragma unroll 8
        for (int f = 0; f < 32; ++f) {
            const float* wrow = Wc + (f << 8) + col0;
            ulonglong2 wA = *(const ulonglong2*)(wrow);
            ulonglong2 wB = *(const ulonglong2*)(wrow + 4);
#pragma unroll
            for (int i = 0; i < 8; ++i) {
                unsigned long long xp = pack2(augS[(er * 8 + i) * AUGSTR + fc * 32 + f]);
                acc[i][0] = fma2(xp, wA.x, acc[i][0]);
                acc[i][1] = fma2(xp, wA.y, acc[i][1]);
                acc[i][2] = fma2(xp, wB.x, acc[i][2]);
                acc[i][3] = fma2(xp, wB.y, acc[i][3]);
            }
        }
    }
#pragma unroll
    for (int i = 0; i < 8; ++i) {
        float4 v0, v1;
        unpack2(acc[i][0], v0.x, v0.y); unpack2(acc[i][1], v0.z, v0.w);
        unpack2(acc[i][2], v1.x, v1.y); unpack2(acc[i][3], v1.z, v1.w);
        v0.x = fmaxf(v0.x, 0.f); v0.y = fmaxf(v0.y, 0.f);
        v0.z = fmaxf(v0.z, 0.f); v0.w = fmaxf(v0.w, 0.f);
        v1.x = fmaxf(v1.x, 0.f); v1.y = fmaxf(v1.y, 0.f);
        v1.z = fmaxf(v1.z, 0.f); v1.w = fmaxf(v1.w, 0.f);
        *(float4*)(p1S + (er * 8 + i) * P1STR + col0)     = v0;
        *(float4*)(p1S + (er * 8 + i) * P1STR + col0 + 4) = v1;
    }

    // ---- layer 2: 256 -> 256 (output relu -> augS reused as p2) ----
    {
        float4 t0 = *(const float4*)(bo2 + col0);
        float4 t1 = *(const float4*)(bo2 + col0 + 4);
        unsigned long long c0 = packab(t0.x, t0.y), c1 = packab(t0.z, t0.w);
        unsigned long long c2 = packab(t1.x, t1.y), c3 = packab(t1.z, t1.w);
#pragma unroll
        for (int i = 0; i < 8; ++i) {
            acc[i][0] = c0; acc[i][1] = c1; acc[i][2] = c2; acc[i][3] = c3;
        }
    }
#pragma unroll 1
    for (int fc = 0; fc < 8; ++fc) {
        __syncthreads();   // also guarantees p1S writes visible on fc==0
        const float* wsrc = Wo2 + fc * 32 * 256;
        for (int idx = tid; idx < 32 * 64; idx += 128)
            *(float4*)(Wc + ((idx >> 6) << 8) + ((idx & 63) << 2)) =
                *(const float4*)(wsrc + ((idx >> 6) << 8) + ((idx & 63) << 2));
        __syncthreads();
#pragma unroll 8
        for (int f = 0; f < 32; ++f) {
            const float* wrow = Wc + (f << 8) + col0;
            ulonglong2 wA = *(const ulonglong2*)(wrow);
            ulonglong2 wB = *(const ulonglong2*)(wrow + 4);
#pragma unroll
            for (int i = 0; i < 8; ++i) {
                unsigned long long xp = pack2(p1S[(er * 8 + i) * P1STR + fc * 32 + f]);
                acc[i][0] = fma2(xp, wA.x, acc[i][0]);
                acc[i][1] = fma2(xp, wA.y, acc[i][1]);
                acc[i][2] = fma2(xp, wB.x, acc[i][2]);
                acc[i][3] = fma2(xp, wB.y, acc[i][3]);
            }
        }
    }
    __syncthreads();   // all augS (layer-1 input) reads done before overwrite
#pragma unroll
    for (int i = 0; i < 8; ++i) {
        float4 v0, v1;
        unpack2(acc[i][0], v0.x, v0.y); unpack2(acc[i][1], v0.z, v0.w);
        unpack2(acc[i][2], v1.x, v1.y); unpack2(acc[i][3], v1.z, v1.w);
        v0.x = fmaxf(v0.x, 0.f); v0.y = fmaxf(v0.y, 0.f);
        v0.z = fmaxf(v0.z, 0.f); v0.w = fmaxf(v0.w, 0.f);
        v1.x = fmaxf(v1.x, 0.f); v1.y = fmaxf(v1.y, 0.f);
        v1.z = fmaxf(v1.z, 0.f); v1.w = fmaxf(v1.w, 0.f);
        *(float4*)(augS + (er * 8 + i) * AUGSTR + col0)     = v0;
        *(float4*)(augS + (er * 8 + i) * AUGSTR + col0 + 4) = v1;
    }

    // ---- layer 3: 256 -> 128, + residual ----
    unsigned long long a3[8][2];
    {
        float4 tb = *(const float4*)(bo3 + (cg << 2));
        unsigned long long c0 = packab(tb.x, tb.y), c1 = packab(tb.z, tb.w);
#pragma unroll
        for (int i = 0; i < 8; ++i) { a3[i][0] = c0; a3[i][1] = c1; }
    }
#pragma unroll 1
    for (int fc = 0; fc < 8; ++fc) {
        __syncthreads();   // p2 writes visible on fc==0
        const float* wsrc = Wo3 + fc * 32 * 128;
        for (int idx = tid; idx < 32 * 32; idx += 128)
            *(float4*)(Wc + ((idx >> 5) << 7) + ((idx & 31) << 2)) =
                *(const float4*)(wsrc + ((idx >> 5) << 7) + ((idx & 31) << 2));
        __syncthreads();
#pragma unroll 8
        for (int f = 0; f < 32; ++f) {
            const float* wrow = Wc + (f << 7) + (cg << 2);
            ulonglong2 wA = *(const ulonglong2*)(wrow);
#pragma unroll
            for (int i = 0; i < 8; ++i) {
                unsigned long long xp = pack2(augS[(er * 8 + i) * AUGSTR + fc * 32 + f]);
                a3[i][0] = fma2(xp, wA.x, a3[i][0]);
                a3[i][1] = fma2(xp, wA.y, a3[i][1]);
            }
        }
    }
#pragma unroll
    for (int i = 0; i < 8; ++i) {
        int r = r0 + er * 8 + i;
        float4 res = *(const float4*)(inputs + ((size_t)(b * NN) + r) * FF + (cg << 2));
        float x0, x1;
        unpack2(a3[i][0], x0, x1); res.x += x0; res.y += x1;
        unpack2(a3[i][1], x0, x1); res.z += x0; res.w += x1;
        *(float4*)(out + ((size_t)(b * NN) + r) * FF + (cg << 2)) = res;
    }
}

// =====================================================================
extern "C" void kernel_launch(void* const* d_in, const int* in_sizes, int n_in,
                              void* d_out, int out_size)
{
    const float* inputs   = (const float*)d_in[0];
    const float* rel_type = (const float*)d_in[1];
    // d_in[2] rel_rec, d_in[3] rel_send: analytic, unused
    const float* W1  = (const float*)d_in[4];
    const float* b1  = (const float*)d_in[5];
    const float* W2  = (const float*)d_in[6];
    const float* b2  = (const float*)d_in[7];
    const float* Wo1 = (const float*)d_in[8];
    const float* bo1 = (const float*)d_in[9];
    const float* Wo2 = (const float*)d_in[10];
    const float* bo2 = (const float*)d_in[11];
    const float* Wo3 = (const float*)d_in[12];
    const float* bo3 = (const float*)d_in[13];
    float* out = (float*)d_out;

    float* agg;
    cudaGetSymbolAddress((void**)&agg, g_agg);

    const int smemA = (64 * XSTR * 2 + 32 * 256 + 256) * 4;           // 166,912 B
    const int smemB = (32 * AUGSTR + 32 * P1STR + 32 * 256) * 4;      // 115,712 B
    cudaFuncSetAttribute(edge_mlp_kernel, cudaFuncAttributeMaxDynamicSharedMemorySize, smemA);
    cudaFuncSetAttribute(out_mlp_kernel, cudaFuncAttributeMaxDynamicSharedMemorySize, smemB);

    edge_mlp_kernel<<<dim3(NN, BB), 256, smemA>>>(inputs, rel_type, W1, b1, W2, b2, agg);
    out_mlp_kernel<<<dim3(2, BB), 128, smemB>>>(inputs, agg, Wo1, bo1, Wo2, bo2, Wo3, bo3, out);
}

// round 5
// speedup vs baseline: 3.1787x; 3.1787x over previous
#include <cuda_runtime.h>
#include <cuda_bf16.h>
#include <cstdint>

#define BB 32
#define NN 64
#define FF 128
#define KK 4
#define EE 4032

// ---------------- static device scratch (no allocations) ----------------
__device__ __align__(16) unsigned char g_w1img[KK * 2 * 256 * 272];  // 557,056 B
__device__ __align__(16) unsigned char g_w2img[KK * 2 * 256 * 528];  // 1,081,344 B
__device__ __align__(16) uint32_t g_ximg_hi[BB * NN * 64];           // bf16 pairs
__device__ __align__(16) uint32_t g_ximg_lo[BB * NN * 64];
__device__ float g_hbase[KK * BB * NN * 256];                        // 8 MB
__device__ float g_agg[BB * NN * 256];                               // 2 MB

// ---------------- helpers ----------------
__device__ __forceinline__ uint32_t smem_u32(const void* p) {
    uint32_t a;
    asm("{ .reg .u64 t; cvta.to.shared.u64 t, %1; cvt.u32.u64 %0, t; }" : "=r"(a) : "l"(p));
    return a;
}
__device__ __forceinline__ void split2(float2 v, uint32_t& hi, uint32_t& lo) {
    __nv_bfloat162 h2 = __float22bfloat162_rn(v);
    float2 r = make_float2(v.x - __bfloat162float(h2.x), v.y - __bfloat162float(h2.y));
    __nv_bfloat162 l2 = __float22bfloat162_rn(r);
    hi = reinterpret_cast<uint32_t&>(h2);
    lo = reinterpret_cast<uint32_t&>(l2);
}
__device__ __forceinline__ void ldm4(uint32_t addr, uint32_t r[4]) {
    asm volatile("ldmatrix.sync.aligned.m8n8.x4.shared.b16 {%0,%1,%2,%3}, [%4];"
                 : "=r"(r[0]), "=r"(r[1]), "=r"(r[2]), "=r"(r[3]) : "r"(addr));
}
__device__ __forceinline__ void mma_bf16(float* c, const uint32_t* a, uint32_t b0, uint32_t b1) {
    asm volatile(
        "mma.sync.aligned.m16n8k16.row.col.f32.bf16.bf16.f32 "
        "{%0,%1,%2,%3}, {%4,%5,%6,%7}, {%8,%9}, {%0,%1,%2,%3};"
        : "+f"(c[0]), "+f"(c[1]), "+f"(c[2]), "+f"(c[3])
        : "r"(a[0]), "r"(a[1]), "r"(a[2]), "r"(a[3]), "r"(b0), "r"(b1));
}
__device__ __forceinline__ void cpa16(uint32_t dst, const void* src) {
    asm volatile("cp.async.cg.shared.global [%0], [%1], 16;" :: "r"(dst), "l"(src));
}
#define CP_COMMIT() asm volatile("cp.async.commit_group;" ::: "memory")
#define CP_WAIT0()  asm volatile("cp.async.wait_group 0;" ::: "memory")

// ---------------- SMEM map (bytes) for edge kernel ----------------
// X stride 272 (68 words, %32==4 -> conflict-free ldmatrix). H/W2 stride 528.
// NOTE: W2 region aliases the X region; X is therefore RE-GATHERED at the top
// of every k iteration (it is clobbered by layer 2 of the previous iteration).
#define SM_XHI   0        // 128*272 = 34816
#define SM_XLO   34816
#define SM_W1HI  69632    // 32*272 = 8704
#define SM_W1LO  78336
#define SM_HHI   87040    // 128*528 = 67584
#define SM_HLO   154624
#define SM_W2HI  0        // 64*528 = 33792 (aliases X region during L2)
#define SM_W2LO  33792
#define SM_HBS   222208   // 2 nodes * 256 f32
#define SM_B2S   224256   // 256 f32
#define SM_RTS   225280   // 128 rows * 4 f32
#define SM_AGGS  227328   // 4 * 256 f32
#define SM_TOTAL 231424

// =====================================================================
// Prep: weight images Wt[n][f] bf16 hi/lo with padded rows.
// src element (kt, n, f) = W[kt*65536 + (koff+f)*256 + n]
// =====================================================================
__global__ void __launch_bounds__(256)
prep_w_kernel(const float* __restrict__ W, int koff, unsigned char* __restrict__ img, int rstride)
{
    __shared__ float ts[32][33];
    const int f0 = blockIdx.x * 32, nn0 = blockIdx.y * 32, kt = blockIdx.z;
    const int tid = threadIdx.x;
    const float* Wk = W + (size_t)kt * 65536;
#pragma unroll
    for (int p = 0; p < 4; ++p) {
        int fr = (tid >> 5) + p * 8, nl = tid & 31;
        ts[fr][nl] = Wk[(size_t)(koff + f0 + fr) * 256 + nn0 + nl];
    }
    __syncthreads();
#pragma unroll
    for (int p = 0; p < 2; ++p) {
        int idx = tid + p * 256;
        int nr = idx >> 4, wp = idx & 15;
        uint32_t hi, lo;
        split2(make_float2(ts[2 * wp][nr], ts[2 * wp + 1][nr]), hi, lo);
        size_t rb = (size_t)(nn0 + nr) * rstride + (f0 + 2 * wp) * 2;
        *(uint32_t*)(img + (size_t)(kt * 2 + 0) * 256 * rstride + rb) = hi;
        *(uint32_t*)(img + (size_t)(kt * 2 + 1) * 256 * rstride + rb) = lo;
    }
}

// inputs -> bf16 hi/lo images (plain [B][N][F] layout, as 32-bit pairs)
__global__ void __launch_bounds__(256)
prep_x_kernel(const float* __restrict__ inputs, uint32_t* __restrict__ xhi, uint32_t* __restrict__ xlo)
{
    int idx = blockIdx.x * 256 + threadIdx.x;
    float2 v = ((const float2*)inputs)[idx];
    uint32_t hi, lo;
    split2(v, hi, lo);
    xhi[idx] = hi;
    xlo[idx] = lo;
}

// hbase[k][b][n][:] = b1[k] + inputs[b][n] @ W1[k][0:128]   (fp32)
__global__ void __launch_bounds__(256)
hbase_kernel(const float* __restrict__ inputs, const float* __restrict__ W1,
             const float* __restrict__ b1, float* __restrict__ hbase)
{
    __shared__ float xs[NN * FF];
    int k = blockIdx.x, b = blockIdx.y;
    for (int i = threadIdx.x; i < NN * FF / 4; i += 256)
        ((float4*)xs)[i] = ((const float4*)(inputs + (size_t)b * NN * FF))[i];
    __syncthreads();
    int h = threadIdx.x;
    const float* Wk = W1 + (size_t)k * 65536;
    float bias = b1[k * 256 + h];
#pragma unroll 1
    for (int nt = 0; nt < 4; ++nt) {
        float acc[16];
#pragma unroll
        for (int i = 0; i < 16; ++i) acc[i] = bias;
#pragma unroll 4
        for (int f = 0; f < 128; ++f) {
            float w = Wk[(size_t)f * 256 + h];
            const float* xp = xs + (nt * 16) * 128 + f;
#pragma unroll
            for (int i = 0; i < 16; ++i) acc[i] = fmaf(xp[i * 128], w, acc[i]);
        }
#pragma unroll
        for (int i = 0; i < 16; ++i)
            hbase[(((size_t)k * BB + b) * NN + nt * 16 + i) * 256 + h] = acc[i];
    }
}

// =====================================================================
// Edge kernel: block = (node pair, batch), 256 threads = 8 warps.
// bf16 mma.sync with 3-split precision; fused gather/relu/weight/aggregate.
// =====================================================================
__global__ void __launch_bounds__(256, 1)
edge_kernel(const float* __restrict__ rel_type,
            const unsigned char* __restrict__ w1img, const unsigned char* __restrict__ w2img,
            const uint32_t* __restrict__ ximg_hi, const uint32_t* __restrict__ ximg_lo,
            const float* __restrict__ b2, const float* __restrict__ hbase,
            float* __restrict__ agg)
{
    extern __shared__ char smem[];
    const uint32_t sb = smem_u32(smem);
    const int tid = threadIdx.x;
    const int lane = tid & 31, w = tid >> 5;
    const int n0 = blockIdx.x * 2, b = blockIdx.y;

    if (tid < 128) {   // rel_type tile [128 rows][4]
        int node = n0 + (tid >> 6), le = tid & 63;
        float4 v = make_float4(0.f, 0.f, 0.f, 0.f);
        if (le < 63) v = *(const float4*)(rel_type + ((size_t)b * EE + node * 63 + le) * KK);
        *(float4*)(smem + SM_RTS + tid * 16) = v;
    }
    for (int i = tid; i < 1024; i += 256) ((float*)(smem + SM_AGGS))[i] = 0.f;

    // lane geometry for ldmatrix / fragments
    const int g = lane >> 2, tg = lane & 3;
    const int arow = lane & 15;
    const uint32_t aoff = (uint32_t)((lane >> 4) << 4);
    const int brow = (lane & 7) + ((lane >> 4) << 3);
    const uint32_t boff = (uint32_t)((lane & 8) << 1);

#pragma unroll 1
    for (int k = 0; k < KK; ++k) {
        __syncthreads();   // retire previous k's W2 (aliased with X) reads

        // ---- (re)gather X: sender features hi/lo bf16, row = edge ----
        for (int t = tid; t < 2048; t += 256) {
            int r = t >> 4, sgi = t & 15;
            int node = n0 + (r >> 6), le = r & 63;
            uint32_t d = r * 272 + sgi * 16;
            if (le < 63) {
                int j = le + (le >= node);
                size_t so = (size_t)(b * 64 + j) * 64 + sgi * 4;
                cpa16(sb + SM_XHI + d, ximg_hi + so);
                cpa16(sb + SM_XLO + d, ximg_lo + so);
            } else {
                float4 z = make_float4(0.f, 0.f, 0.f, 0.f);
                *(float4*)(smem + SM_XHI + d) = z;
                *(float4*)(smem + SM_XLO + d) = z;
            }
        }
        CP_COMMIT();

        if (tid < 128)
            ((float4*)(smem + SM_HBS))[tid] =
                ((const float4*)(hbase + (((size_t)k * BB + b) * NN + n0) * 256))[tid];
        else if (tid < 192)
            ((float4*)(smem + SM_B2S))[tid - 128] = ((const float4*)(b2 + k * 256))[tid - 128];

        // -------- layer 1: 8 slabs of 32 cols, A = X (k=128) --------
        const int m0 = w * 16;
#pragma unroll 1
        for (int s = 0; s < 8; ++s) {
            __syncthreads();
            for (int t = tid; t < 1088; t += 256) {
                int im = t >= 544;
                uint32_t off = (uint32_t)(t - im * 544) * 16;
                cpa16(sb + (im ? SM_W1LO : SM_W1HI) + off,
                      w1img + (size_t)((k * 2 + im) * 256 + s * 32) * 272 + off);
            }
            CP_COMMIT(); CP_WAIT0();
            __syncthreads();

            float c[4][4] = {};
#pragma unroll 1
            for (int sp = 0; sp < 3; ++sp) {
                uint32_t Ab = sb + (sp == 2 ? SM_XLO : SM_XHI) + (m0 + arow) * 272 + aoff;
                uint32_t Bb = sb + (sp == 1 ? SM_W1LO : SM_W1HI) + brow * 272 + boff;
#pragma unroll
                for (int ks = 0; ks < 8; ++ks) {
                    uint32_t a[4], b0[4], b1[4];
                    ldm4(Ab + ks * 32, a);
                    ldm4(Bb + ks * 32, b0);
                    ldm4(Bb + 16 * 272 + ks * 32, b1);
                    mma_bf16(c[0], a, b0[0], b0[1]);
                    mma_bf16(c[1], a, b0[2], b0[3]);
                    mma_bf16(c[2], a, b1[0], b1[1]);
                    mma_bf16(c[3], a, b1[2], b1[3]);
                }
            }
            // epilogue: relu(D + hbase) -> H hi/lo
            {
                const float* hbs = (const float*)(smem + SM_HBS);
                int r0 = m0 + g, r1 = m0 + g + 8;
                const float* h0 = hbs + (r0 >> 6) * 256;
                const float* h1 = hbs + (r1 >> 6) * 256;
#pragma unroll
                for (int tn = 0; tn < 4; ++tn) {
                    int col = s * 32 + tn * 8 + 2 * tg;
                    float v00 = fmaxf(c[tn][0] + h0[col], 0.f);
                    float v01 = fmaxf(c[tn][1] + h0[col + 1], 0.f);
                    float v10 = fmaxf(c[tn][2] + h1[col], 0.f);
                    float v11 = fmaxf(c[tn][3] + h1[col + 1], 0.f);
                    uint32_t hi0, lo0, hi1, lo1;
                    split2(make_float2(v00, v01), hi0, lo0);
                    split2(make_float2(v10, v11), hi1, lo1);
                    *(uint32_t*)(smem + SM_HHI + r0 * 528 + col * 2) = hi0;
                    *(uint32_t*)(smem + SM_HLO + r0 * 528 + col * 2) = lo0;
                    *(uint32_t*)(smem + SM_HHI + r1 * 528 + col * 2) = hi1;
                    *(uint32_t*)(smem + SM_HLO + r1 * 528 + col * 2) = lo1;
                }
            }
        }

        // -------- layer 2: 4 slabs of 64 cols, A = H (k=256) --------
        const int wm = w >> 1, wn = w & 1;
        const int m2 = wm * 32;
        const float* rts = (const float*)(smem + SM_RTS);
        const float* b2s = (const float*)(smem + SM_B2S);
        float* aggS = (float*)(smem + SM_AGGS);
#pragma unroll 1
        for (int s = 0; s < 4; ++s) {
            __syncthreads();   // retire X reads (s==0) / previous W2 reads
            for (int t = tid; t < 4224; t += 256) {
                int im = t >= 2112;
                uint32_t off = (uint32_t)(t - im * 2112) * 16;
                cpa16(sb + (im ? SM_W2LO : SM_W2HI) + off,
                      w2img + (size_t)((k * 2 + im) * 256 + s * 64) * 528 + off);
            }
            CP_COMMIT(); CP_WAIT0();
            __syncthreads();

            float c2[2][4][4] = {};
#pragma unroll 1
            for (int sp = 0; sp < 3; ++sp) {
                uint32_t Ab = sb + (sp == 2 ? SM_HLO : SM_HHI) + (m2 + arow) * 528 + aoff;
                uint32_t Bb = sb + (sp == 1 ? SM_W2LO : SM_W2HI) + (wn * 32 + brow) * 528 + boff;
#pragma unroll
                for (int ks = 0; ks < 16; ++ks) {
                    uint32_t a0[4], a1[4], b0[4], b1[4];
                    ldm4(Ab + ks * 32, a0);
                    ldm4(Ab + 16 * 528 + ks * 32, a1);
                    ldm4(Bb + ks * 32, b0);
                    ldm4(Bb + 16 * 528 + ks * 32, b1);
                    mma_bf16(c2[0][0], a0, b0[0], b0[1]);
                    mma_bf16(c2[0][1], a0, b0[2], b0[3]);
                    mma_bf16(c2[0][2], a0, b1[0], b1[1]);
                    mma_bf16(c2[0][3], a0, b1[2], b1[3]);
                    mma_bf16(c2[1][0], a1, b0[0], b0[1]);
                    mma_bf16(c2[1][1], a1, b0[2], b0[3]);
                    mma_bf16(c2[1][2], a1, b1[0], b1[1]);
                    mma_bf16(c2[1][3], a1, b1[2], b1[3]);
                }
            }
            // epilogue: relu(D+b2) * rel_type, reduce over rows -> aggS
            float p[4][2];
#pragma unroll
            for (int tn = 0; tn < 4; ++tn) { p[tn][0] = 0.f; p[tn][1] = 0.f; }
#pragma unroll
            for (int mt = 0; mt < 2; ++mt) {
                int r0 = m2 + mt * 16 + g, r1 = r0 + 8;
                float w0 = rts[r0 * 4 + k], w1 = rts[r1 * 4 + k];
#pragma unroll
                for (int tn = 0; tn < 4; ++tn) {
                    int col = s * 64 + wn * 32 + tn * 8 + 2 * tg;
                    p[tn][0] += w0 * fmaxf(c2[mt][tn][0] + b2s[col], 0.f)
                              + w1 * fmaxf(c2[mt][tn][2] + b2s[col], 0.f);
                    p[tn][1] += w0 * fmaxf(c2[mt][tn][1] + b2s[col + 1], 0.f)
                              + w1 * fmaxf(c2[mt][tn][3] + b2s[col + 1], 0.f);
                }
            }
#pragma unroll
            for (int off = 4; off <= 16; off <<= 1)
#pragma unroll
                for (int tn = 0; tn < 4; ++tn) {
                    p[tn][0] += __shfl_xor_sync(0xffffffff, p[tn][0], off);
                    p[tn][1] += __shfl_xor_sync(0xffffffff, p[tn][1], off);
                }
            if (g == 0) {
#pragma unroll
                for (int tn = 0; tn < 4; ++tn) {
                    int col = s * 64 + wn * 32 + tn * 8 + 2 * tg;
                    aggS[wm * 256 + col]     += p[tn][0];
                    aggS[wm * 256 + col + 1] += p[tn][1];
                }
            }
        }
    }

    __syncthreads();
    {
        const float* aggS = (const float*)(smem + SM_AGGS);
        for (int t = tid; t < 512; t += 256) {
            int ni = t >> 8, m = t & 255;
            agg[((size_t)b * NN + n0 + ni) * 256 + m] =
                aggS[(2 * ni) * 256 + m] + aggS[(2 * ni + 1) * 256 + m];
        }
    }
}

// =====================================================================
// Output MLP 384->256->256->128 + residual (fp32 f32x2), 16 rows/block.
// =====================================================================
#define AUGSTR 388
#define P1STR 260
__device__ __forceinline__ unsigned long long pack2(float x) {
    unsigned long long r; asm("mov.b64 %0, {%1, %1};" : "=l"(r) : "f"(x)); return r;
}
__device__ __forceinline__ unsigned long long packab(float a, float b) {
    unsigned long long r; asm("mov.b64 %0, {%1, %2};" : "=l"(r) : "f"(a), "f"(b)); return r;
}
__device__ __forceinline__ void unpack2(unsigned long long v, float& a, float& b) {
    asm("mov.b64 {%0, %1}, %2;" : "=f"(a), "=f"(b) : "l"(v));
}
__device__ __forceinline__ unsigned long long fma2(unsigned long long a,
                                                   unsigned long long b,
                                                   unsigned long long c) {
    unsigned long long d;
    asm("fma.rn.f32x2 %0, %1, %2, %3;" : "=l"(d) : "l"(a), "l"(b), "l"(c));
    return d;
}

__global__ void __launch_bounds__(128)
out_mlp_kernel(const float* __restrict__ inputs, const float* __restrict__ agg,
               const float* __restrict__ Wo1, const float* __restrict__ bo1,
               const float* __restrict__ Wo2, const float* __restrict__ bo2,
               const float* __restrict__ Wo3, const float* __restrict__ bo3,
               float* __restrict__ out)
{
    extern __shared__ float sm[];
    float* augS = sm;                    // [16][AUGSTR], later reused for p2
    float* p1S  = augS + 16 * AUGSTR;    // [16][P1STR]
    float* Wc   = p1S + 16 * P1STR;      // [32][256]

    const int qtr = blockIdx.x, b = blockIdx.y;
    const int r0 = qtr * 16, tid = threadIdx.x;
    const int cg = tid & 31, er = tid >> 5, col0 = cg << 3;

    for (int idx = tid; idx < 16 * 96; idx += 128) {
        int r = idx / 96, c4 = idx % 96;
        float4 v;
        if (c4 < 32) v = *(const float4*)(inputs + ((size_t)(b * NN) + r0 + r) * FF + (c4 << 2));
        else         v = *(const float4*)(agg + ((size_t)(b * NN) + r0 + r) * 256 + ((c4 - 32) << 2));
        *(float4*)(augS + r * AUGSTR + (c4 << 2)) = v;
    }

    unsigned long long acc[4][4];
    {
        float4 t0 = *(const float4*)(bo1 + col0);
        float4 t1 = *(const float4*)(bo1 + col0 + 4);
        unsigned long long c0 = packab(t0.x, t0.y), c1 = packab(t0.z, t0.w);
        unsigned long long c2 = packab(t1.x, t1.y), c3 = packab(t1.z, t1.w);
#pragma unroll
        for (int i = 0; i < 4; ++i) { acc[i][0]=c0; acc[i][1]=c1; acc[i][2]=c2; acc[i][3]=c3; }
    }
#pragma unroll 1
    for (int fc = 0; fc < 12; ++fc) {
        __syncthreads();
        const float* wsrc = Wo1 + fc * 32 * 256;
        for (int idx = tid; idx < 32 * 64; idx += 128)
            *(float4*)(Wc + ((idx >> 6) << 8) + ((idx & 63) << 2)) =
                *(const float4*)(wsrc + ((idx >> 6) << 8) + ((idx & 63) << 2));
        __syncthreads();
#pragma unroll 8
        for (int f = 0; f < 32; ++f) {
            const float* wrow = Wc + (f << 8) + col0;
            ulonglong2 wA = *(const ulonglong2*)(wrow);
            ulonglong2 wB = *(const ulonglong2*)(wrow + 4);
#pragma unroll
            for (int i = 0; i < 4; ++i) {
                unsigned long long xp = pack2(augS[(er * 4 + i) * AUGSTR + fc * 32 + f]);
                acc[i][0] = fma2(xp, wA.x, acc[i][0]); acc[i][1] = fma2(xp, wA.y, acc[i][1]);
                acc[i][2] = fma2(xp, wB.x, acc[i][2]); acc[i][3] = fma2(xp, wB.y, acc[i][3]);
            }
        }
    }
#pragma unroll
    for (int i = 0; i < 4; ++i) {
        float4 v0, v1;
        unpack2(acc[i][0], v0.x, v0.y); unpack2(acc[i][1], v0.z, v0.w);
        unpack2(acc[i][2], v1.x, v1.y); unpack2(acc[i][3], v1.z, v1.w);
        v0.x=fmaxf(v0.x,0.f); v0.y=fmaxf(v0.y,0.f); v0.z=fmaxf(v0.z,0.f); v0.w=fmaxf(v0.w,0.f);
        v1.x=fmaxf(v1.x,0.f); v1.y=fmaxf(v1.y,0.f); v1.z=fmaxf(v1.z,0.f); v1.w=fmaxf(v1.w,0.f);
        *(float4*)(p1S + (er * 4 + i) * P1STR + col0)     = v0;
        *(float4*)(p1S + (er * 4 + i) * P1STR + col0 + 4) = v1;
    }

    {
        float4 t0 = *(const float4*)(bo2 + col0);
        float4 t1 = *(const float4*)(bo2 + col0 + 4);
        unsigned long long c0 = packab(t0.x, t0.y), c1 = packab(t0.z, t0.w);
        unsigned long long c2 = packab(t1.x, t1.y), c3 = packab(t1.z, t1.w);
#pragma unroll
        for (int i = 0; i < 4; ++i) { acc[i][0]=c0; acc[i][1]=c1; acc[i][2]=c2; acc[i][3]=c3; }
    }
#pragma unroll 1
    for (int fc = 0; fc < 8; ++fc) {
        __syncthreads();
        const float* wsrc = Wo2 + fc * 32 * 256;
        for (int idx = tid; idx < 32 * 64; idx += 128)
            *(float4*)(Wc + ((idx >> 6) << 8) + ((idx & 63) << 2)) =
                *(const float4*)(wsrc + ((idx >> 6) << 8) + ((idx & 63) << 2));
        __syncthreads();
#pragma unroll 8
        for (int f = 0; f < 32; ++f) {
            const float* wrow = Wc + (f << 8) + col0;
            ulonglong2 wA = *(const ulonglong2*)(wrow);
            ulonglong2 wB = *(const ulonglong2*)(wrow + 4);
#pragma unroll
            for (int i = 0; i < 4; ++i) {
                unsigned long long xp = pack2(p1S[(er * 4 + i) * P1STR + fc * 32 + f]);
                acc[i][0] = fma2(xp, wA.x, acc[i][0]); acc[i][1] = fma2(xp, wA.y, acc[i][1]);
                acc[i][2] = fma2(xp, wB.x, acc[i][2]); acc[i][3] = fma2(xp, wB.y, acc[i][3]);
            }
        }
    }
    __syncthreads();
#pragma unroll
    for (int i = 0; i < 4; ++i) {
        float4 v0, v1;
        unpack2(acc[i][0], v0.x, v0.y); unpack2(acc[i][1], v0.z, v0.w);
        unpack2(acc[i][2], v1.x, v1.y); unpack2(acc[i][3], v1.z, v1.w);
        v0.x=fmaxf(v0.x,0.f); v0.y=fmaxf(v0.y,0.f); v0.z=fmaxf(v0.z,0.f); v0.w=fmaxf(v0.w,0.f);
        v1.x=fmaxf(v1.x,0.f); v1.y=fmaxf(v1.y,0.f); v1.z=fmaxf(v1.z,0.f); v1.w=fmaxf(v1.w,0.f);
        *(float4*)(augS + (er * 4 + i) * AUGSTR + col0)     = v0;
        *(float4*)(augS + (er * 4 + i) * AUGSTR + col0 + 4) = v1;
    }

    unsigned long long a3[4][2];
    {
        float4 tb4 = *(const float4*)(bo3 + (cg << 2));
        unsigned long long c0 = packab(tb4.x, tb4.y), c1 = packab(tb4.z, tb4.w);
#pragma unroll
        for (int i = 0; i < 4; ++i) { a3[i][0] = c0; a3[i][1] = c1; }
    }
#pragma unroll 1
    for (int fc = 0; fc < 8; ++fc) {
        __syncthreads();
        const float* wsrc = Wo3 + fc * 32 * 128;
        for (int idx = tid; idx < 32 * 32; idx += 128)
            *(float4*)(Wc + ((idx >> 5) << 7) + ((idx & 31) << 2)) =
                *(const float4*)(wsrc + ((idx >> 5) << 7) + ((idx & 31) << 2));
        __syncthreads();
#pragma unroll 8
        for (int f = 0; f < 32; ++f) {
            const float* wrow = Wc + (f << 7) + (cg << 2);
            ulonglong2 wA = *(const ulonglong2*)(wrow);
#pragma unroll
            for (int i = 0; i < 4; ++i) {
                unsigned long long xp = pack2(augS[(er * 4 + i) * AUGSTR + fc * 32 + f]);
                a3[i][0] = fma2(xp, wA.x, a3[i][0]); a3[i][1] = fma2(xp, wA.y, a3[i][1]);
            }
        }
    }
#pragma unroll
    for (int i = 0; i < 4; ++i) {
        int r = r0 + er * 4 + i;
        float4 res = *(const float4*)(inputs + ((size_t)(b * NN) + r) * FF + (cg << 2));
        float x0, x1;
        unpack2(a3[i][0], x0, x1); res.x += x0; res.y += x1;
        unpack2(a3[i][1], x0, x1); res.z += x0; res.w += x1;
        *(float4*)(out + ((size_t)(b * NN) + r) * FF + (cg << 2)) = res;
    }
}

// =====================================================================
extern "C" void kernel_launch(void* const* d_in, const int* in_sizes, int n_in,
                              void* d_out, int out_size)
{
    const float* inputs   = (const float*)d_in[0];
    const float* rel_type = (const float*)d_in[1];
    const float* W1  = (const float*)d_in[4];
    const float* b1  = (const float*)d_in[5];
    const float* W2  = (const float*)d_in[6];
    const float* b2  = (const float*)d_in[7];
    const float* Wo1 = (const float*)d_in[8];
    const float* bo1 = (const float*)d_in[9];
    const float* Wo2 = (const float*)d_in[10];
    const float* bo2 = (const float*)d_in[11];
    const float* Wo3 = (const float*)d_in[12];
    const float* bo3 = (const float*)d_in[13];
    float* out = (float*)d_out;

    float *agg, *hb;
    unsigned char *w1i, *w2i;
    uint32_t *xhi, *xlo;
    cudaGetSymbolAddress((void**)&agg, g_agg);
    cudaGetSymbolAddress((void**)&hb, g_hbase);
    cudaGetSymbolAddress((void**)&w1i, g_w1img);
    cudaGetSymbolAddress((void**)&w2i, g_w2img);
    cudaGetSymbolAddress((void**)&xhi, g_ximg_hi);
    cudaGetSymbolAddress((void**)&xlo, g_ximg_lo);

    const int smemB = (16 * AUGSTR + 16 * P1STR + 32 * 256) * 4;  // 74240
    cudaFuncSetAttribute(edge_kernel, cudaFuncAttributeMaxDynamicSharedMemorySize, SM_TOTAL);
    cudaFuncSetAttribute(out_mlp_kernel, cudaFuncAttributeMaxDynamicSharedMemorySize, smemB);

    prep_x_kernel<<<BB * NN * 64 / 256, 256>>>(inputs, xhi, xlo);
    prep_w_kernel<<<dim3(4, 8, 4), 256>>>(W1, 128, w1i, 272);   // sender half of W1
    prep_w_kernel<<<dim3(8, 8, 4), 256>>>(W2, 0, w2i, 528);
    hbase_kernel<<<dim3(KK, BB), 256>>>(inputs, W1, b1, hb);
    edge_kernel<<<dim3(NN / 2, BB), 256, SM_TOTAL>>>(rel_type, w1i, w2i, xhi, xlo, b2, hb, agg);
    out_mlp_kernel<<<dim3(4, BB), 128, smemB>>>(inputs, agg, Wo1, bo1, Wo2, bo2, Wo3, bo3, out);
}